// round 6
// baseline (speedup 1.0000x reference)
#include <cuda_runtime.h>
#include <cstdint>

// PointOnSurfaceLoss: B=8, M=512, N=8192
// inputs: keypoint [B,3,M] f32, pc [B,3,N] f32, sn [B,3,N] f32
// output: loss [B,M,1,1] f32  (B*M = 4096 floats)
//
// Stage1: 512 blocks = 128 keypoint-groups x 4 N-quarters. Block = 256 thr
//         (8 warps). lane = keypoint (broadcast LDS), warps split the tile.
// Stage2: 4-way lexicographic (d, n) reduce per keypoint + epilogue.

#define BATCH 8
#define MM    512
#define NN    8192
#define TN    2048             // points per quarter-tile
#define NPAIR (TN / 2)         // 1024 pairs
#define WPB   8                // warps per stage1 block
#define PW    (NPAIR / WPB)    // 128 pairs per warp
#define NGRP  (BATCH * MM / 32)  // 128 keypoint groups
#define EPSV  1e-7f

__device__ float g_part_d[NGRP * 4 * 32];
__device__ int   g_part_n[NGRP * 4 * 32];

union f2u  { float2 f; uint64_t u; };
union f4u2 { float4 f; ulonglong2 u; };   // .u.x = (f.x,f.y) pair, .u.y = (f.z,f.w)

__device__ __forceinline__ uint64_t add2(uint64_t a, uint64_t b) {
    uint64_t r; asm("add.rn.f32x2 %0, %1, %2;" : "=l"(r) : "l"(a), "l"(b)); return r;
}
__device__ __forceinline__ uint64_t mul2(uint64_t a, uint64_t b) {
    uint64_t r; asm("mul.rn.f32x2 %0, %1, %2;" : "=l"(r) : "l"(a), "l"(b)); return r;
}
__device__ __forceinline__ uint64_t fma2(uint64_t a, uint64_t b, uint64_t c) {
    uint64_t r; asm("fma.rn.f32x2 %0, %1, %2, %3;" : "=l"(r) : "l"(a), "l"(b), "l"(c)); return r;
}
__device__ __forceinline__ uint64_t pack2(float lo, float hi) {
    uint64_t r; asm("mov.b64 %0, {%1, %2};" : "=l"(r) : "f"(lo), "f"(hi)); return r;
}

// evaluate pair p (f32x2 xy from xy4, f32x2 z): returns min dist + code 2t+bit
#define EVAL_PAIR(XYP, ZP, T, DOUT, COUT)                                  \
    do {                                                                   \
        const uint64_t dx_ = add2((XYP).u.x, nkx2);                        \
        const uint64_t dy_ = add2((XYP).u.y, nky2);                        \
        const uint64_t dz_ = add2((ZP),      nkz2);                        \
        uint64_t s_ = mul2(dx_, dx_);                                      \
        s_ = fma2(dy_, dy_, s_);                                           \
        s_ = fma2(dz_, dz_, s_);                                           \
        f2u d2_; d2_.u = s_;                                               \
        if (d2_.f.y < d2_.f.x) { DOUT = d2_.f.y; COUT = 2 * (T) + 1; }     \
        else                   { DOUT = d2_.f.x; COUT = 2 * (T);     }     \
    } while (0)

__global__ __launch_bounds__(256, 4)
void pos_loss_stage1(const float* __restrict__ keypoint,
                     const float* __restrict__ pc)
{
    __shared__ float4 xy4[NPAIR];   // 16 KB: (x0,x1,y0,y1) per pair
    __shared__ float2 zz2[NPAIR];   //  8 KB: (z0,z1) per pair
    __shared__ float  red_d[WPB * 32];
    __shared__ int    red_n[WPB * 32];

    const int blk  = blockIdx.x;       // 512
    const int grp  = blk >> 2;         // keypoint group 0..127
    const int q    = blk & 3;          // N quarter
    const int b    = grp >> 4;
    const int tid  = threadIdx.x;
    const int wid  = tid >> 5;
    const int lane = tid & 31;
    const int m    = (grp & 15) * 32 + lane;

    const float* kpb = keypoint + (size_t)b * 3 * MM;
    const float kx = kpb[0 * MM + m];
    const float ky = kpb[1 * MM + m];
    const float kz = kpb[2 * MM + m];
    const uint64_t nkx2 = pack2(-kx, -kx);
    const uint64_t nky2 = pack2(-ky, -ky);
    const uint64_t nkz2 = pack2(-kz, -kz);

    const float* pcb = pc + (size_t)b * 3 * NN;
    const int n0 = q * TN;

    // tile load: build interleaved pair layout (L2 hits)
    {
        const float2* gx = (const float2*)(pcb + 0 * NN + n0);
        const float2* gy = (const float2*)(pcb + 1 * NN + n0);
        const float2* gz = (const float2*)(pcb + 2 * NN + n0);
        #pragma unroll
        for (int i = tid; i < NPAIR; i += 256) {
            const float2 x2 = gx[i];
            const float2 y2 = gy[i];
            xy4[i] = make_float4(x2.x, x2.y, y2.x, y2.y);
            zz2[i] = gz[i];
        }
    }
    __syncthreads();

    float best  = 3.4e38f;
    int   bcode = 0;                      // 2*t + bit, t local to warp (0..127)
    const int pbase = wid * PW;           // this warp's first pair
    const float4* z4 = (const float4*)zz2;   // z4[j] = z-pairs (2j, 2j+1)

    #pragma unroll 4
    for (int t0 = 0; t0 < PW; t0 += 4) {
        f4u2 v0, v1, v2, v3, zA, zB;
        v0.f = xy4[pbase + t0 + 0];
        v1.f = xy4[pbase + t0 + 1];
        v2.f = xy4[pbase + t0 + 2];
        v3.f = xy4[pbase + t0 + 3];
        zA.f = z4[(pbase + t0) >> 1];     // z pairs for t0, t0+1
        zB.f = z4[((pbase + t0) >> 1) + 1];

        float d0, d1, d2, d3; int c0, c1, c2, c3;
        EVAL_PAIR(v0, zA.u.x, t0 + 0, d0, c0);
        EVAL_PAIR(v1, zA.u.y, t0 + 1, d1, c1);
        EVAL_PAIR(v2, zB.u.x, t0 + 2, d2, c2);
        EVAL_PAIR(v3, zB.u.y, t0 + 3, d3, c3);

        // tournament tree (strict < keeps lower t on ties)
        float d01, d23; int c01, c23;
        if (d1 < d0) { d01 = d1; c01 = c1; } else { d01 = d0; c01 = c0; }
        if (d3 < d2) { d23 = d3; c23 = c3; } else { d23 = d2; c23 = c2; }
        float dT; int cT;
        if (d23 < d01) { dT = d23; cT = c23; } else { dT = d01; cT = c01; }
        if (dT < best) { best = dT; bcode = cT; }
    }

    // n within batch = n0 + wid*256 + bcode (ascending in (wid, t, bit))
    red_d[wid * 32 + lane] = best;
    red_n[wid * 32 + lane] = n0 + wid * (PW * 2) + bcode;
    __syncthreads();

    if (wid == 0) {
        float bd = red_d[lane];
        int   bn = red_n[lane];
        #pragma unroll
        for (int w = 1; w < WPB; ++w) {
            const float od = red_d[w * 32 + lane];
            const int   on = red_n[w * 32 + lane];
            if (od < bd || (od == bd && on < bn)) { bd = od; bn = on; }
        }
        const int sidx = (grp * 4 + q) * 32 + lane;
        g_part_d[sidx] = bd;
        g_part_n[sidx] = bn;
    }
}

__global__ __launch_bounds__(256)
void pos_loss_stage2(const float* __restrict__ keypoint,
                     const float* __restrict__ pc,
                     const float* __restrict__ sn,
                     float* __restrict__ out)
{
    const int t    = blockIdx.x * 256 + threadIdx.x;   // 0..4095
    const int grp  = t >> 5;
    const int lane = t & 31;
    const int b    = grp >> 4;
    const int m    = (grp & 15) * 32 + lane;

    // 4-way lexicographic reduce (quarters cover ascending n-ranges)
    float bd = g_part_d[(grp * 4 + 0) * 32 + lane];
    int   bn = g_part_n[(grp * 4 + 0) * 32 + lane];
    #pragma unroll
    for (int q = 1; q < 4; ++q) {
        const float od = g_part_d[(grp * 4 + q) * 32 + lane];
        const int   on = g_part_n[(grp * 4 + q) * 32 + lane];
        if (od < bd || (od == bd && on < bn)) { bd = od; bn = on; }
    }

    const float* kpb = keypoint + (size_t)b * 3 * MM;
    const float kx = kpb[0 * MM + m];
    const float ky = kpb[1 * MM + m];
    const float kz = kpb[2 * MM + m];

    const float* pcb = pc + (size_t)b * 3 * NN;
    const float* snb = sn + (size_t)b * 3 * NN;
    const float px = pcb[0 * NN + bn];
    const float py = pcb[1 * NN + bn];
    const float pz = pcb[2 * NN + bn];
    const float sx = snb[0 * NN + bn];
    const float sy = snb[1 * NN + bn];
    const float sz = snb[2 * NN + bn];

    const float dx = kx - px;
    const float dy = ky - py;
    const float dz = kz - pz;
    const float nrm = sqrtf(dx * dx + dy * dy + dz * dz);
    const float dot = (sx * dx + sy * dy + sz * dz) / (nrm + EPSV);
    out[b * MM + m] = dot * dot;
}

extern "C" void kernel_launch(void* const* d_in, const int* in_sizes, int n_in,
                              void* d_out, int out_size)
{
    const float* keypoint = (const float*)d_in[0]; // 8*3*512
    const float* pc       = (const float*)d_in[1]; // 8*3*8192
    const float* sn       = (const float*)d_in[2]; // 8*3*8192
    float* out            = (float*)d_out;         // 4096

    pos_loss_stage1<<<NGRP * 4, 256>>>(keypoint, pc);          // 512 blocks
    pos_loss_stage2<<<BATCH * MM / 256, 256>>>(keypoint, pc, sn, out);  // 16 blocks
}

// round 7
// speedup vs baseline: 1.0152x; 1.0152x over previous
#include <cuda_runtime.h>
#include <cstdint>

// PointOnSurfaceLoss: B=8, M=512, N=8192
// inputs: keypoint [B,3,M] f32, pc [B,3,N] f32, sn [B,3,N] f32
// output: loss [B,M,1,1] f32  (B*M = 4096 floats)
//
// Single fused kernel: 512 blocks = 128 keypoint-groups x 4 N-quarters.
// Partial argmins published as packed uint64 keys via atomicMax(~key);
// last-arriving block per group runs the epilogue inline and resets state.

#define BATCH 8
#define MM    512
#define NN    8192
#define TN    2048             // points per quarter-tile
#define NPAIR (TN / 2)         // 1024 pairs
#define WPB   8                // warps per block
#define PW    (NPAIR / WPB)    // 128 pairs per warp
#define NGRP  (BATCH * MM / 32)  // 128 keypoint groups
#define EPSV  1e-7f

// zero-initialized device state; reset to zero by the finalizing block each launch
__device__ unsigned long long g_inv[NGRP * 32];   // ~key, max-reduced
__device__ unsigned int       g_cnt[NGRP];        // arrival counters

union f2u  { float2 f; uint64_t u; };
union f4u2 { float4 f; ulonglong2 u; };

__device__ __forceinline__ uint64_t add2(uint64_t a, uint64_t b) {
    uint64_t r; asm("add.rn.f32x2 %0, %1, %2;" : "=l"(r) : "l"(a), "l"(b)); return r;
}
__device__ __forceinline__ uint64_t mul2(uint64_t a, uint64_t b) {
    uint64_t r; asm("mul.rn.f32x2 %0, %1, %2;" : "=l"(r) : "l"(a), "l"(b)); return r;
}
__device__ __forceinline__ uint64_t fma2(uint64_t a, uint64_t b, uint64_t c) {
    uint64_t r; asm("fma.rn.f32x2 %0, %1, %2, %3;" : "=l"(r) : "l"(a), "l"(b), "l"(c)); return r;
}
__device__ __forceinline__ uint64_t pack2(float lo, float hi) {
    uint64_t r; asm("mov.b64 %0, {%1, %2};" : "=l"(r) : "f"(lo), "f"(hi)); return r;
}

#define EVAL_PAIR(XYP, ZP, T, DOUT, COUT)                                  \
    do {                                                                   \
        const uint64_t dx_ = add2((XYP).u.x, nkx2);                        \
        const uint64_t dy_ = add2((XYP).u.y, nky2);                        \
        const uint64_t dz_ = add2((ZP),      nkz2);                        \
        uint64_t s_ = mul2(dx_, dx_);                                      \
        s_ = fma2(dy_, dy_, s_);                                           \
        s_ = fma2(dz_, dz_, s_);                                           \
        f2u d2_; d2_.u = s_;                                               \
        if (d2_.f.y < d2_.f.x) { DOUT = d2_.f.y; COUT = 2 * (T) + 1; }     \
        else                   { DOUT = d2_.f.x; COUT = 2 * (T);     }     \
    } while (0)

__global__ __launch_bounds__(256, 4)
void pos_loss_fused(const float* __restrict__ keypoint,
                    const float* __restrict__ pc,
                    const float* __restrict__ sn,
                    float* __restrict__ out)
{
    __shared__ float4 xy4[NPAIR];            // 16 KB: (x0,x1,y0,y1) per pair
    __shared__ float2 zz2[NPAIR];            //  8 KB: (z0,z1) per pair
    __shared__ unsigned long long red[WPB * 32];
    __shared__ int s_is_last;

    const int blk  = blockIdx.x;             // 512
    const int grp  = blk >> 2;               // keypoint group 0..127
    const int q    = blk & 3;                // N quarter
    const int b    = grp >> 4;
    const int tid  = threadIdx.x;
    const int wid  = tid >> 5;
    const int lane = tid & 31;
    const int m    = (grp & 15) * 32 + lane;

    const float* kpb = keypoint + (size_t)b * 3 * MM;
    const float kx = kpb[0 * MM + m];
    const float ky = kpb[1 * MM + m];
    const float kz = kpb[2 * MM + m];
    const uint64_t nkx2 = pack2(-kx, -kx);
    const uint64_t nky2 = pack2(-ky, -ky);
    const uint64_t nkz2 = pack2(-kz, -kz);

    const float* pcb = pc + (size_t)b * 3 * NN;
    const int n0 = q * TN;

    // tile load: interleaved pair layout (L2 hits)
    {
        const float2* gx = (const float2*)(pcb + 0 * NN + n0);
        const float2* gy = (const float2*)(pcb + 1 * NN + n0);
        const float2* gz = (const float2*)(pcb + 2 * NN + n0);
        #pragma unroll
        for (int i = tid; i < NPAIR; i += 256) {
            const float2 x2 = gx[i];
            const float2 y2 = gy[i];
            xy4[i] = make_float4(x2.x, x2.y, y2.x, y2.y);
            zz2[i] = gz[i];
        }
    }
    __syncthreads();

    float best  = 3.4e38f;
    int   bcode = 0;                          // 2*t + bit, t local to warp
    const int pbase = wid * PW;
    const float4* z4 = (const float4*)zz2;

    #pragma unroll 4
    for (int t0 = 0; t0 < PW; t0 += 4) {
        f4u2 v0, v1, v2, v3, zA, zB;
        v0.f = xy4[pbase + t0 + 0];
        v1.f = xy4[pbase + t0 + 1];
        v2.f = xy4[pbase + t0 + 2];
        v3.f = xy4[pbase + t0 + 3];
        zA.f = z4[(pbase + t0) >> 1];
        zB.f = z4[((pbase + t0) >> 1) + 1];

        float d0, d1, d2, d3; int c0, c1, c2, c3;
        EVAL_PAIR(v0, zA.u.x, t0 + 0, d0, c0);
        EVAL_PAIR(v1, zA.u.y, t0 + 1, d1, c1);
        EVAL_PAIR(v2, zB.u.x, t0 + 2, d2, c2);
        EVAL_PAIR(v3, zB.u.y, t0 + 3, d3, c3);

        float d01, d23; int c01, c23;
        if (d1 < d0) { d01 = d1; c01 = c1; } else { d01 = d0; c01 = c0; }
        if (d3 < d2) { d23 = d3; c23 = c3; } else { d23 = d2; c23 = c2; }
        float dT; int cT;
        if (d23 < d01) { dT = d23; cT = c23; } else { dT = d01; cT = c01; }
        if (dT < best) { best = dT; bcode = cT; }
    }

    // packed key: (bits(d2) << 32) | n  — uint64 min == lexicographic (d, n) min
    {
        const int n = n0 + wid * (PW * 2) + bcode;
        uint32_t dbits; asm("mov.b32 %0, %1;" : "=r"(dbits) : "f"(best));
        red[wid * 32 + lane] = ((unsigned long long)dbits << 32) | (unsigned)n;
    }
    __syncthreads();

    // warp 0: combine 8 warp-partials, publish via atomicMax(~key), arrive
    if (wid == 0) {
        unsigned long long bk = red[lane];
        #pragma unroll
        for (int w = 1; w < WPB; ++w) {
            const unsigned long long ok = red[w * 32 + lane];
            if (ok < bk) bk = ok;
        }
        atomicMax(&g_inv[grp * 32 + lane], ~bk);
        __threadfence();
    }
    if (tid == 0) {
        const unsigned int prev = atomicAdd(&g_cnt[grp], 1u);
        s_is_last = (prev == 3u);
    }
    __syncthreads();

    // last-arriving block for this group: final reduce + epilogue + state reset
    if (s_is_last && wid == 0) {
        __threadfence();
        // atomic read (RMW at L2) of the fully-reduced key
        const unsigned long long inv = atomicMax(&g_inv[grp * 32 + lane], 0ULL);
        const unsigned long long key = ~inv;
        const int bn = (int)(key & 0xFFFFFFFFu);

        const float px = pcb[0 * NN + bn];
        const float py = pcb[1 * NN + bn];
        const float pz = pcb[2 * NN + bn];
        const float* snb = sn + (size_t)b * 3 * NN;
        const float sx = snb[0 * NN + bn];
        const float sy = snb[1 * NN + bn];
        const float sz = snb[2 * NN + bn];
        const float dx = kx - px;
        const float dy = ky - py;
        const float dz = kz - pz;
        const float nrm = sqrtf(dx * dx + dy * dy + dz * dz);
        const float dot = (sx * dx + sy * dy + sz * dz) / (nrm + EPSV);
        out[b * MM + m] = dot * dot;

        // reset for next graph replay (deterministic)
        atomicExch(&g_inv[grp * 32 + lane], 0ULL);
        if (lane == 0) atomicExch(&g_cnt[grp], 0u);
    }
}

extern "C" void kernel_launch(void* const* d_in, const int* in_sizes, int n_in,
                              void* d_out, int out_size)
{
    const float* keypoint = (const float*)d_in[0]; // 8*3*512
    const float* pc       = (const float*)d_in[1]; // 8*3*8192
    const float* sn       = (const float*)d_in[2]; // 8*3*8192
    float* out            = (float*)d_out;         // 4096

    pos_loss_fused<<<NGRP * 4, 256>>>(keypoint, pc, sn, out);  // 512 blocks
}

// round 8
// speedup vs baseline: 1.0381x; 1.0225x over previous
#include <cuda_runtime.h>
#include <cstdint>

// PointOnSurfaceLoss: B=8, M=512, N=8192
// inputs: keypoint [B,3,M] f32, pc [B,3,N] f32, sn [B,3,N] f32
// output: loss [B,M,1,1] f32  (B*M = 4096 floats)
//
// Single fused kernel: 1024 blocks = 128 keypoint-groups x 8 N-splits.
// Partial argmins published as packed uint64 keys via atomicMax(~key);
// last-arriving block per group runs an OUTLINED epilogue and resets state.

#define BATCH 8
#define MM    512
#define NN    8192
#define NSPLIT 8
#define TN    (NN / NSPLIT)    // 1024 points per split-tile
#define NPAIR (TN / 2)         // 512 pairs
#define WPB   8                // warps per block
#define PW    (NPAIR / WPB)    // 64 pairs per warp
#define NGRP  (BATCH * MM / 32)  // 128 keypoint groups
#define EPSV  1e-7f

// zero-initialized device state; reset to zero by the finalizing block each launch
__device__ unsigned long long g_inv[NGRP * 32];   // ~key, max-reduced
__device__ unsigned int       g_cnt[NGRP];        // arrival counters

union f2u  { float2 f; uint64_t u; };
union f4u2 { float4 f; ulonglong2 u; };

__device__ __forceinline__ uint64_t add2(uint64_t a, uint64_t b) {
    uint64_t r; asm("add.rn.f32x2 %0, %1, %2;" : "=l"(r) : "l"(a), "l"(b)); return r;
}
__device__ __forceinline__ uint64_t mul2(uint64_t a, uint64_t b) {
    uint64_t r; asm("mul.rn.f32x2 %0, %1, %2;" : "=l"(r) : "l"(a), "l"(b)); return r;
}
__device__ __forceinline__ uint64_t fma2(uint64_t a, uint64_t b, uint64_t c) {
    uint64_t r; asm("fma.rn.f32x2 %0, %1, %2, %3;" : "=l"(r) : "l"(a), "l"(b), "l"(c)); return r;
}
__device__ __forceinline__ uint64_t pack2(float lo, float hi) {
    uint64_t r; asm("mov.b64 %0, {%1, %2};" : "=l"(r) : "f"(lo), "f"(hi)); return r;
}

#define EVAL_PAIR(XYP, ZP, T, DOUT, COUT)                                  \
    do {                                                                   \
        const uint64_t dx_ = add2((XYP).u.x, nkx2);                        \
        const uint64_t dy_ = add2((XYP).u.y, nky2);                        \
        const uint64_t dz_ = add2((ZP),      nkz2);                        \
        uint64_t s_ = mul2(dx_, dx_);                                      \
        s_ = fma2(dy_, dy_, s_);                                           \
        s_ = fma2(dz_, dz_, s_);                                           \
        f2u d2_; d2_.u = s_;                                               \
        if (d2_.f.y < d2_.f.x) { DOUT = d2_.f.y; COUT = 2 * (T) + 1; }     \
        else                   { DOUT = d2_.f.x; COUT = 2 * (T);     }     \
    } while (0)

// Cold path: runs once per group (by the 8th-arriving block's warp 0).
// Outlined so its register demand doesn't inflate the hot loop.
__device__ __noinline__ void finalize_group(const float* __restrict__ keypoint,
                                            const float* __restrict__ pc,
                                            const float* __restrict__ sn,
                                            float* __restrict__ out,
                                            int grp, int lane)
{
    const int b = grp >> 4;
    const int m = (grp & 15) * 32 + lane;

    __threadfence();
    // atomic read (RMW at L2) of the fully-reduced key, then decode
    const unsigned long long inv = atomicMax(&g_inv[grp * 32 + lane], 0ULL);
    const int bn = (int)((~inv) & 0xFFFFFFFFu);

    const float* kpb = keypoint + (size_t)b * 3 * MM;
    const float kx = kpb[0 * MM + m];
    const float ky = kpb[1 * MM + m];
    const float kz = kpb[2 * MM + m];

    const float* pcb = pc + (size_t)b * 3 * NN;
    const float* snb = sn + (size_t)b * 3 * NN;
    const float px = pcb[0 * NN + bn];
    const float py = pcb[1 * NN + bn];
    const float pz = pcb[2 * NN + bn];
    const float sx = snb[0 * NN + bn];
    const float sy = snb[1 * NN + bn];
    const float sz = snb[2 * NN + bn];

    const float dx = kx - px;
    const float dy = ky - py;
    const float dz = kz - pz;
    const float nrm = sqrtf(dx * dx + dy * dy + dz * dz);
    const float dot = (sx * dx + sy * dy + sz * dz) / (nrm + EPSV);
    out[b * MM + m] = dot * dot;

    // reset for next graph replay (deterministic)
    atomicExch(&g_inv[grp * 32 + lane], 0ULL);
    if (lane == 0) atomicExch(&g_cnt[grp], 0u);
}

__global__ __launch_bounds__(256, 5)
void pos_loss_fused(const float* __restrict__ keypoint,
                    const float* __restrict__ pc,
                    const float* __restrict__ sn,
                    float* __restrict__ out)
{
    __shared__ float4 xy4[NPAIR];            // 8 KB: (x0,x1,y0,y1) per pair
    __shared__ float2 zz2[NPAIR];            // 4 KB: (z0,z1) per pair
    __shared__ unsigned long long red[WPB * 32];
    __shared__ int s_is_last;

    const int blk  = blockIdx.x;             // 1024
    const int grp  = blk >> 3;               // keypoint group 0..127
    const int spl  = blk & 7;                // N split
    const int b    = grp >> 4;
    const int tid  = threadIdx.x;
    const int wid  = tid >> 5;
    const int lane = tid & 31;
    const int m    = (grp & 15) * 32 + lane;

    uint64_t nkx2, nky2, nkz2;
    {
        const float* kpb = keypoint + (size_t)b * 3 * MM;
        const float kx = kpb[0 * MM + m];
        const float ky = kpb[1 * MM + m];
        const float kz = kpb[2 * MM + m];
        nkx2 = pack2(-kx, -kx);
        nky2 = pack2(-ky, -ky);
        nkz2 = pack2(-kz, -kz);
    }

    const float* pcb = pc + (size_t)b * 3 * NN;
    const int n0 = spl * TN;

    // tile load: interleaved pair layout (L2 hits)
    {
        const float2* gx = (const float2*)(pcb + 0 * NN + n0);
        const float2* gy = (const float2*)(pcb + 1 * NN + n0);
        const float2* gz = (const float2*)(pcb + 2 * NN + n0);
        #pragma unroll
        for (int i = tid; i < NPAIR; i += 256) {
            const float2 x2 = gx[i];
            const float2 y2 = gy[i];
            xy4[i] = make_float4(x2.x, x2.y, y2.x, y2.y);
            zz2[i] = gz[i];
        }
    }
    __syncthreads();

    float best  = 3.4e38f;
    int   bcode = 0;                          // 2*t + bit, t local to warp
    const int pbase = wid * PW;
    const float4* z4 = (const float4*)zz2;

    #pragma unroll 4
    for (int t0 = 0; t0 < PW; t0 += 4) {
        f4u2 v0, v1, v2, v3, zA, zB;
        v0.f = xy4[pbase + t0 + 0];
        v1.f = xy4[pbase + t0 + 1];
        v2.f = xy4[pbase + t0 + 2];
        v3.f = xy4[pbase + t0 + 3];
        zA.f = z4[(pbase + t0) >> 1];
        zB.f = z4[((pbase + t0) >> 1) + 1];

        float d0, d1, d2, d3; int c0, c1, c2, c3;
        EVAL_PAIR(v0, zA.u.x, t0 + 0, d0, c0);
        EVAL_PAIR(v1, zA.u.y, t0 + 1, d1, c1);
        EVAL_PAIR(v2, zB.u.x, t0 + 2, d2, c2);
        EVAL_PAIR(v3, zB.u.y, t0 + 3, d3, c3);

        float d01, d23; int c01, c23;
        if (d1 < d0) { d01 = d1; c01 = c1; } else { d01 = d0; c01 = c0; }
        if (d3 < d2) { d23 = d3; c23 = c3; } else { d23 = d2; c23 = c2; }
        float dT; int cT;
        if (d23 < d01) { dT = d23; cT = c23; } else { dT = d01; cT = c01; }
        if (dT < best) { best = dT; bcode = cT; }
    }

    // packed key: (bits(d2) << 32) | n  — uint64 min == lexicographic (d, n) min
    {
        const int n = n0 + wid * (PW * 2) + bcode;
        uint32_t dbits; asm("mov.b32 %0, %1;" : "=r"(dbits) : "f"(best));
        red[wid * 32 + lane] = ((unsigned long long)dbits << 32) | (unsigned)n;
    }
    __syncthreads();

    // warp 0: combine 8 warp-partials, publish via atomicMax(~key)
    if (wid == 0) {
        unsigned long long bk = red[lane];
        #pragma unroll
        for (int w = 1; w < WPB; ++w) {
            const unsigned long long ok = red[w * 32 + lane];
            if (ok < bk) bk = ok;
        }
        atomicMax(&g_inv[grp * 32 + lane], ~bk);
        __threadfence();
    }
    if (tid == 0) {
        const unsigned int prev = atomicAdd(&g_cnt[grp], 1u);
        s_is_last = (prev == (NSPLIT - 1u));
    }
    __syncthreads();

    if (s_is_last && wid == 0) {
        finalize_group(keypoint, pc, sn, out, grp, lane);
    }
}

extern "C" void kernel_launch(void* const* d_in, const int* in_sizes, int n_in,
                              void* d_out, int out_size)
{
    const float* keypoint = (const float*)d_in[0]; // 8*3*512
    const float* pc       = (const float*)d_in[1]; // 8*3*8192
    const float* sn       = (const float*)d_in[2]; // 8*3*8192
    float* out            = (float*)d_out;         // 4096

    pos_loss_fused<<<NGRP * NSPLIT, 256>>>(keypoint, pc, sn, out);  // 1024 blocks
}